// round 1
// baseline (speedup 1.0000x reference)
#include <cuda_runtime.h>
#include <math.h>

// Problem dims
#define LSn 2
#define BSn 64
#define Tn 64
#define Dn 128
#define NHn 128
#define NEn 128
#define ROWSn 4096   // 64 ensembles * 64 batch
#define G4n 512      // 4*NH

// d_out float offsets: (filter_out, filter_cov, X_new, Cov_new, ll)
#define OUT_FO   0
#define OUT_FCOV 64
#define OUT_X    4160
#define OUT_COV  2101312
#define OUT_LL   4198464

// ---- device scratch (no allocations allowed) ----
__device__ float g_h[2][2][ROWSn*NHn];     // [layer][parity][row*128+n]
__device__ float g_c[2][ROWSn*NHn];
__device__ float g_hseq[Tn][ROWSn*NHn];    // layer0 outputs per t (134MB)
__device__ float g_xproj[ROWSn*G4n];       // [(t*64+b)*512 + col]
__device__ float g_bsum[2][G4n];
__device__ float g_up[LSn*BSn*NHn*NEn];
__device__ float g_Am[LSn*BSn*NHn*NEn];
__device__ float g_HA[BSn*NEn];
__device__ float g_innov[BSn*NEn];
__device__ float g_P[BSn*BSn];
__device__ float g_Pinv[BSn*BSn];
__device__ float g_T2[BSn*NEn];
__device__ float g_T1[NEn*NEn];
__device__ float g_rmean[LSn*BSn*NHn];
__device__ float g_AY[BSn*NEn];
__device__ float g_fout[BSn];
__device__ float g_fcov[BSn*BSn];

__device__ __forceinline__ float sigm(float x){ return 1.f/(1.f + expf(-x)); }

#define GEMM_CHUNK(AS,BS_,ACC,TX,TY)                                   \
  _Pragma("unroll 4")                                                  \
  for (int k2=0;k2<32;k2++){                                           \
    float a_[8], b_[8];                                                \
    *(float4*)&a_[0] = *(const float4*)&AS[k2][(TY)*8];                \
    *(float4*)&a_[4] = *(const float4*)&AS[k2][(TY)*8+4];              \
    *(float4*)&b_[0] = *(const float4*)&BS_[k2][(TX)*8];               \
    *(float4*)&b_[4] = *(const float4*)&BS_[k2][(TX)*8+4];             \
    _Pragma("unroll")                                                  \
    for (int ii=0;ii<8;ii++){                                          \
      _Pragma("unroll")                                                \
      for (int jj=0;jj<8;jj++) ACC[ii][jj] += a_[ii]*b_[jj];           \
    }                                                                  \
  }

// ---- init h0/c0 from uhi: h0[j,l,b,k] = uhi[l,b,k,j], c0 from j+64 ----
__global__ void k_init(const float* __restrict__ uhi){
  int idx = blockIdx.x*blockDim.x + threadIdx.x;     // 2^20 total
  int k = idx & 127, b = (idx>>7)&63, j = (idx>>13)&63, l = idx>>19;
  long base = (((long)(l*BSn+b))*NHn + k)*NEn;
  g_h[l][0][(j*64+b)*NHn + k] = uhi[base + j];
  g_c[l][(j*64+b)*NHn + k]    = uhi[base + 64 + j];
}

__global__ void k_bias(const float* __restrict__ bih, const float* __restrict__ bhh){
  int idx = blockIdx.x*blockDim.x + threadIdx.x;
  if (idx < 1024){
    int l = idx >> 9, c = idx & 511;
    g_bsum[l][c] = bih[l*512+c] + bhh[l*512+c];
  }
}

// ---- layer-0 input projection over all timesteps: (4096x512) = X(4096x128)@Wi0^T + bias ----
__global__ __launch_bounds__(256) void k_xproj(const float* __restrict__ x,
                                               const float* __restrict__ Wi0){
  __shared__ __align__(16) float As[32][132];
  __shared__ __align__(16) float Bs[32][132];
  int tid = threadIdx.x, tx = tid & 15, ty = tid >> 4;
  int rb = blockIdx.x*128, cb = blockIdx.y*128;
  float acc[8][8] = {};
  for (int kc=0; kc<128; kc+=32){
    for (int i=tid;i<4096;i+=256){
      int r = i>>5, kk = i&31;
      int gr = rb + r, b = gr & 63, t = gr >> 6;
      As[kk][r] = x[(b*Tn + t)*Dn + kc + kk];
    }
    for (int i=tid;i<4096;i+=256){
      int c = i>>5, kk = i&31;
      Bs[kk][c] = Wi0[(cb + c)*Dn + kc + kk];
    }
    __syncthreads();
    GEMM_CHUNK(As,Bs,acc,tx,ty);
    __syncthreads();
  }
  #pragma unroll
  for (int r=0;r<8;r++){
    int gr = rb + ty*8 + r;
    #pragma unroll
    for (int u=0;u<8;u++){
      int gc = cb + tx*8 + u;
      g_xproj[gr*512 + gc] = acc[r][u] + g_bsum[0][gc];
    }
  }
}

// ---- fused LSTM step: gates GEMM + pointwise update ----
// Block: 128 rows x 32 n (x4 gates, interleaved col = n_local*4 + gate)
template<int LAYER>
__global__ __launch_bounds__(256) void k_step(const float* __restrict__ Wh,
                                              const float* __restrict__ Wi,
                                              int t){
  __shared__ __align__(16) float As[32][132];
  __shared__ __align__(16) float Bs[32][132];
  int tid = threadIdx.x, tx = tid & 15, ty = tid >> 4;
  int rb = blockIdx.x*128, n0 = blockIdx.y*32;
  int rp = t & 1, wp = rp ^ 1;
  const float* Hst = g_h[LAYER][rp];
  float acc[8][8] = {};

  for (int kc=0; kc<128; kc+=32){
    for (int i=tid;i<4096;i+=256){
      int r = i>>5, kk = i&31;
      As[kk][r] = Hst[(rb+r)*NHn + kc + kk];
    }
    for (int i=tid;i<4096;i+=256){
      int c = i>>5, kk = i&31;
      int wrow = ((c&3)<<7) + n0 + (c>>2);
      Bs[kk][c] = Wh[wrow*NHn + kc + kk];
    }
    __syncthreads();
    GEMM_CHUNK(As,Bs,acc,tx,ty);
    __syncthreads();
  }
  if (LAYER == 1){
    const float* Hp = &g_hseq[t][0];
    for (int kc=0; kc<128; kc+=32){
      for (int i=tid;i<4096;i+=256){
        int r = i>>5, kk = i&31;
        As[kk][r] = Hp[(rb+r)*NHn + kc + kk];
      }
      for (int i=tid;i<4096;i+=256){
        int c = i>>5, kk = i&31;
        int wrow = ((c&3)<<7) + n0 + (c>>2);
        Bs[kk][c] = Wi[wrow*NHn + kc + kk];
      }
      __syncthreads();
      GEMM_CHUNK(As,Bs,acc,tx,ty);
      __syncthreads();
    }
  }
  // epilogue: i,f,g,o -> c,h
  #pragma unroll
  for (int r=0;r<8;r++){
    int row = rb + ty*8 + r;
    int b = row & 63;
    const float* add = (LAYER==0) ? &g_xproj[(t*64+b)*512] : &g_bsum[1][0];
    #pragma unroll
    for (int p=0;p<2;p++){
      int n = n0 + tx*2 + p;
      float gi = acc[r][p*4+0] + add[      n];
      float gf = acc[r][p*4+1] + add[128 + n];
      float gg = acc[r][p*4+2] + add[256 + n];
      float go = acc[r][p*4+3] + add[384 + n];
      float cold = g_c[LAYER][row*NHn + n];
      float cn = sigm(gf)*cold + sigm(gi)*tanhf(gg);
      float hn = sigm(go)*tanhf(cn);
      g_c[LAYER][row*NHn + n] = cn;
      g_h[LAYER][wp][row*NHn + n] = hn;
      if (LAYER == 0) g_hseq[t][row*NHn + n] = hn;
    }
  }
}

// ---- uhi_pred + anomalies A ----
__global__ void k_up(const float* __restrict__ nh, const float* __restrict__ nc,
                     const float* qp, const float* ep){
  int m = blockIdx.x;                      // (l*64+b)*128 + n, 16384
  int j = threadIdx.x;                     // ensemble col 0..127
  int n = m & 127, b = (m>>7)&63, l = m>>13;
  float q = fabsf(*qp), e = fabsf(*ep);
  float v;
  if (j < 64)
    v = g_h[l][0][(j*64+b)*NHn + n] + q * nh[((j*LSn + l)*BSn + b)*NHn + n];
  else {
    int j2 = j - 64;
    v = g_c[l][(j2*64+b)*NHn + n] + e * nc[((j2*LSn + l)*BSn + b)*NHn + n];
  }
  __shared__ float red[128];
  red[j] = v; __syncthreads();
  for (int s=64;s>0;s>>=1){ if (j<s) red[j]+=red[j+s]; __syncthreads(); }
  float mean = red[0]*(1.f/128.f);
  g_up[(long)m*128 + j] = v;
  g_Am[(long)m*128 + j] = v - mean;
}

// ---- hxi, HA, innov ----
__global__ void k_hxi(const float* __restrict__ Hm, const float* __restrict__ y){
  int b = blockIdx.x, N = threadIdx.x;
  __shared__ float Hs[128];
  Hs[N] = Hm[N]; __syncthreads();
  float s = 0.f;
  for (int n=0;n<128;n++) s += g_up[((long)(b*128+n))*128 + N] * Hs[n];
  __shared__ float red[128];
  red[N] = s; __syncthreads();
  for (int st=64;st>0;st>>=1){ if (N<st) red[N]+=red[N+st]; __syncthreads(); }
  float mean = red[0]*(1.f/128.f);
  g_HA[b*128+N] = s - mean;
  g_innov[b*128+N] = y[b] - s;
}

__global__ void k_P(const float* rp){
  int c = blockIdx.x, d = threadIdx.x;
  float s = 0.f;
  for (int N=0;N<128;N++) s += g_HA[c*128+N]*g_HA[d*128+N];
  float r = *rp;
  g_P[c*64+d] = s*(1.f/127.f) + (c==d ? r*r : 0.f);
}

// ---- Gauss-Jordan inverse of P (64x64), one block, 128 threads ----
__global__ void k_inv(){
  __shared__ float M[64][128];
  __shared__ float fcol[64];
  __shared__ int spiv;
  int tid = threadIdx.x;
  for (int e=tid;e<8192;e+=128){
    int r = e>>7, c = e&127;
    M[r][c] = (c<64) ? g_P[r*64+c] : ((c-64)==r ? 1.f : 0.f);
  }
  __syncthreads();
  for (int k=0;k<64;k++){
    if (tid==0){
      int p = k; float best = fabsf(M[k][k]);
      for (int rr=k+1;rr<64;rr++){ float v=fabsf(M[rr][k]); if (v>best){best=v;p=rr;} }
      spiv = p;
    }
    __syncthreads();
    int p = spiv;
    if (p != k){ float tmp = M[k][tid]; M[k][tid] = M[p][tid]; M[p][tid] = tmp; }
    __syncthreads();
    float pv = M[k][k];
    __syncthreads();
    M[k][tid] = M[k][tid] / pv;
    __syncthreads();
    if (tid < 64) fcol[tid] = M[tid][k];
    __syncthreads();
    for (int e=tid;e<8192;e+=128){
      int r = e>>7, c = e&127;
      if (r != k) M[r][c] -= fcol[r]*M[k][c];
    }
    __syncthreads();
  }
  for (int e=tid;e<4096;e+=128){
    int r = e>>6, d = e&63;
    g_Pinv[r*64+d] = M[r][64+d];
  }
}

__global__ void k_T2(){
  int c = blockIdx.x, M = threadIdx.x;
  float s = 0.f;
  for (int d=0;d<64;d++) s += g_Pinv[c*64+d]*g_innov[d*128+M];
  g_T2[c*128+M] = s;
}

__global__ void k_T1(){
  int N = blockIdx.x, M = threadIdx.x;
  __shared__ float HAc[64];
  if (M < 64) HAc[M] = g_HA[M*128 + N];
  __syncthreads();
  float s = 0.f;
  for (int c=0;c<64;c++) s += HAc[c]*g_T2[c*128+M];
  g_T1[N*128+M] = s;
}

// ---- X_new = up + A@T1/127, one block per (l,b) ----
__global__ __launch_bounds__(256) void k_upd(float* __restrict__ out){
  __shared__ __align__(16) float As[32][132];
  __shared__ __align__(16) float Bs[32][132];
  int lb = blockIdx.x;
  int tid = threadIdx.x, tx = tid & 15, ty = tid >> 4;
  const float* Ab = &g_Am[(long)lb*16384];
  float acc[8][8] = {};
  for (int kc=0; kc<128; kc+=32){
    for (int i=tid;i<4096;i+=256){
      int r = i>>5, kk = i&31;
      As[kk][r] = Ab[r*128 + kc + kk];
    }
    for (int i=tid;i<4096;i+=256){
      int c = i&127, kk = i>>7;
      Bs[kk][c] = g_T1[(kc+kk)*128 + c];
    }
    __syncthreads();
    GEMM_CHUNK(As,Bs,acc,tx,ty);
    __syncthreads();
  }
  #pragma unroll
  for (int r=0;r<8;r++){
    int n = ty*8 + r;
    #pragma unroll
    for (int u=0;u<8;u++){
      int Mc = tx*8 + u;
      long idx = (long)lb*16384 + n*128 + Mc;
      out[OUT_X + idx] = g_up[idx] + acc[r][u]*(1.f/127.f);
    }
  }
}

__global__ void k_rmean(const float* __restrict__ out){
  int row = blockIdx.x;                 // (l*64+b)*128 + n
  int M = threadIdx.x;
  float v = out[OUT_X + (long)row*128 + M];
  __shared__ float red[128];
  red[M] = v; __syncthreads();
  for (int s=64;s>0;s>>=1){ if (M<s) red[M]+=red[M+s]; __syncthreads(); }
  if (M==0) g_rmean[row] = red[0]*(1.f/128.f);
}

// ---- Cov_new = An@An^T/127, one block per (l,b) ----
__global__ __launch_bounds__(256) void k_cov(float* __restrict__ out){
  __shared__ __align__(16) float S[32][132];
  int lb = blockIdx.x;
  int tid = threadIdx.x, tx = tid & 15, ty = tid >> 4;
  const float* Xb = out + OUT_X + (long)lb*16384;
  const float* mu = &g_rmean[lb*128];
  float acc[8][8] = {};
  for (int kc=0; kc<128; kc+=32){
    for (int i=tid;i<4096;i+=256){
      int r = i>>5, kk = i&31;
      S[kk][r] = Xb[r*128 + kc + kk] - mu[r];
    }
    __syncthreads();
    GEMM_CHUNK(S,S,acc,tx,ty);
    __syncthreads();
  }
  #pragma unroll
  for (int r=0;r<8;r++){
    int n = ty*8 + r;
    #pragma unroll
    for (int u=0;u<8;u++){
      int m = tx*8 + u;
      out[OUT_COV + (long)lb*16384 + n*128 + m] = acc[r][u]*(1.f/127.f);
    }
  }
}

__global__ void k_Y(const float* __restrict__ Hm, float* __restrict__ out){
  int b = blockIdx.x, N = threadIdx.x;
  __shared__ float Hs[128];
  Hs[N] = Hm[N]; __syncthreads();
  float s = 0.f;
  for (int n=0;n<128;n++) s += out[OUT_X + (long)b*16384 + n*128 + N] * Hs[n];
  __shared__ float red[128];
  red[N] = s; __syncthreads();
  for (int st=64;st>0;st>>=1){ if (N<st) red[N]+=red[N+st]; __syncthreads(); }
  float mean = red[0]*(1.f/128.f);
  g_AY[b*128+N] = s - mean;
  if (N==0){ g_fout[b] = mean; out[OUT_FO + b] = mean; }
}

__global__ void k_fcov(const float* rp, float* __restrict__ out){
  int c = blockIdx.x, d = threadIdx.x;
  float s = 0.f;
  for (int N=0;N<128;N++) s += g_AY[c*128+N]*g_AY[d*128+N];
  float r = *rp;
  float v = s*(1.f/127.f) + (c==d ? r*r : 0.f);
  g_fcov[c*64+d] = v;
  out[OUT_FCOV + c*64+d] = v;
}

// ---- Cholesky + logdet + solve -> ll ----
__global__ void k_ll(const float* __restrict__ y, float* __restrict__ out){
  __shared__ float A[64][65];
  __shared__ float red[64];
  int tid = threadIdx.x;
  for (int c=0;c<64;c++) A[tid][c] = g_fcov[tid*64+c];
  __syncthreads();
  for (int k=0;k<64;k++){
    if (tid==k) A[k][k] = sqrtf(A[k][k]);
    __syncthreads();
    float lkk = A[k][k];
    if (tid>k) A[tid][k] /= lkk;
    __syncthreads();
    if (tid>k){
      float lrk = A[tid][k];
      for (int c=k+1;c<=tid;c++) A[tid][c] -= lrk*A[c][k];
    }
    __syncthreads();
  }
  red[tid] = 2.f*logf(A[tid][tid]);
  __syncthreads();
  for (int s=32;s>0;s>>=1){ if (tid<s) red[tid]+=red[tid+s]; __syncthreads(); }
  if (tid==0){
    float logdet = red[0];
    float z[64];
    for (int k=0;k<64;k++){
      float s = y[k] - g_fout[k];
      for (int j=0;j<k;j++) s -= A[k][j]*z[j];
      z[k] = s / A[k][k];
    }
    float qs = 0.f;
    for (int k=0;k<64;k++) qs += z[k]*z[k];
    out[OUT_LL] = -0.5f*logdet - 0.5f*qs;
  }
}

extern "C" void kernel_launch(void* const* d_in, const int* in_sizes, int n_in,
                              void* d_out, int out_size){
  const float* x    = (const float*)d_in[0];
  const float* y    = (const float*)d_in[1];
  const float* uhi  = (const float*)d_in[2];
  const float* W_ih = (const float*)d_in[3];
  const float* W_hh = (const float*)d_in[4];
  const float* b_ih = (const float*)d_in[5];
  const float* b_hh = (const float*)d_in[6];
  const float* Hm   = (const float*)d_in[7];
  const float* q    = (const float*)d_in[8];
  const float* e    = (const float*)d_in[9];
  const float* r    = (const float*)d_in[10];
  const float* nh   = (const float*)d_in[11];
  const float* nc   = (const float*)d_in[12];
  float* out = (float*)d_out;

  k_init<<<4096, 256>>>(uhi);
  k_bias<<<4, 256>>>(b_ih, b_hh);
  dim3 gproj(32, 4);
  k_xproj<<<gproj, 256>>>(x, W_ih);            // layer 0 input projection (+biases)

  dim3 gs(32, 4);
  for (int t=0; t<Tn; t++)
    k_step<0><<<gs, 256>>>(W_hh, W_ih, t);
  for (int t=0; t<Tn; t++)
    k_step<1><<<gs, 256>>>(W_hh + 512*128, W_ih + 512*128, t);

  k_up<<<16384, 128>>>(nh, nc, q, e);
  k_hxi<<<64, 128>>>(Hm, y);
  k_P<<<64, 64>>>(r);
  k_inv<<<1, 128>>>();
  k_T2<<<64, 128>>>();
  k_T1<<<128, 128>>>();
  k_upd<<<128, 256>>>(out);
  k_rmean<<<16384, 128>>>(out);
  k_cov<<<128, 256>>>(out);
  k_Y<<<64, 128>>>(Hm, out);
  k_fcov<<<64, 64>>>(r, out);
  k_ll<<<1, 64>>>(y, out);
}

// round 2
// speedup vs baseline: 1.0006x; 1.0006x over previous
#include <cuda_runtime.h>
#include <math.h>

// Problem dims
#define LSn 2
#define BSn 64
#define Tn 64
#define Dn 128
#define NHn 128
#define NEn 128
#define ROWSn 4096   // 64 ensembles * 64 batch
#define G4n 512      // 4*NH

// d_out float offsets: (filter_out, filter_cov, X_new, Cov_new, ll)
#define OUT_FO   0
#define OUT_FCOV 64
#define OUT_X    4160
#define OUT_COV  2101312
#define OUT_LL   4198464

// ---- device scratch (no allocations allowed) ----
__device__ float g_h[2][2][ROWSn*NHn];     // [layer][parity][row*128+n]
__device__ float g_c[2][ROWSn*NHn];
__device__ float g_hseq[Tn][ROWSn*NHn];    // layer0 outputs per t (134MB)
__device__ float g_xproj[ROWSn*G4n];       // [(t*64+b)*512 + col]
__device__ float g_bsum[2][G4n];
__device__ float g_up[LSn*BSn*NHn*NEn];
__device__ float g_Am[LSn*BSn*NHn*NEn];
__device__ float g_HA[BSn*NEn];
__device__ float g_innov[BSn*NEn];
__device__ float g_P[BSn*BSn];
__device__ float g_Pinv[BSn*BSn];
__device__ float g_T2[BSn*NEn];
__device__ float g_T1[NEn*NEn];
__device__ float g_rmean[LSn*BSn*NHn];
__device__ float g_AY[BSn*NEn];
__device__ float g_fout[BSn];
__device__ float g_fcov[BSn*BSn];

__device__ __forceinline__ float sigm(float x){ return 1.f/(1.f + expf(-x)); }

#define GEMM_CHUNK(AS,BS_,ACC,TX,TY)                                   \
  _Pragma("unroll 4")                                                  \
  for (int k2=0;k2<32;k2++){                                           \
    float a_[8], b_[8];                                                \
    *(float4*)&a_[0] = *(const float4*)&AS[k2][(TY)*8];                \
    *(float4*)&a_[4] = *(const float4*)&AS[k2][(TY)*8+4];              \
    *(float4*)&b_[0] = *(const float4*)&BS_[k2][(TX)*8];               \
    *(float4*)&b_[4] = *(const float4*)&BS_[k2][(TX)*8+4];             \
    _Pragma("unroll")                                                  \
    for (int ii=0;ii<8;ii++){                                          \
      _Pragma("unroll")                                                \
      for (int jj=0;jj<8;jj++) ACC[ii][jj] += a_[ii]*b_[jj];           \
    }                                                                  \
  }

// ---- init h0/c0 from uhi: h0[j,l,b,k] = uhi[l,b,k,j], c0 from j+64 ----
__global__ void k_init(const float* __restrict__ uhi){
  int idx = blockIdx.x*blockDim.x + threadIdx.x;     // 2^20 total
  int k = idx & 127, b = (idx>>7)&63, j = (idx>>13)&63, l = idx>>19;
  long base = (((long)(l*BSn+b))*NHn + k)*NEn;
  g_h[l][0][(j*64+b)*NHn + k] = uhi[base + j];
  g_c[l][(j*64+b)*NHn + k]    = uhi[base + 64 + j];
}

__global__ void k_bias(const float* __restrict__ bih, const float* __restrict__ bhh){
  int idx = blockIdx.x*blockDim.x + threadIdx.x;
  if (idx < 1024){
    int l = idx >> 9, c = idx & 511;
    g_bsum[l][c] = bih[l*512+c] + bhh[l*512+c];
  }
}

// ---- layer-0 input projection over all timesteps: (4096x512) = X(4096x128)@Wi0^T + bias ----
__global__ __launch_bounds__(256) void k_xproj(const float* __restrict__ x,
                                               const float* __restrict__ Wi0){
  __shared__ __align__(16) float As[32][132];
  __shared__ __align__(16) float Bs[32][132];
  int tid = threadIdx.x, tx = tid & 15, ty = tid >> 4;
  int rb = blockIdx.x*128, cb = blockIdx.y*128;
  float acc[8][8] = {};
  for (int kc=0; kc<128; kc+=32){
    for (int i=tid;i<4096;i+=256){
      int r = i>>5, kk = i&31;
      int gr = rb + r, b = gr & 63, t = gr >> 6;
      As[kk][r] = x[(b*Tn + t)*Dn + kc + kk];
    }
    for (int i=tid;i<4096;i+=256){
      int c = i>>5, kk = i&31;
      Bs[kk][c] = Wi0[(cb + c)*Dn + kc + kk];
    }
    __syncthreads();
    GEMM_CHUNK(As,Bs,acc,tx,ty);
    __syncthreads();
  }
  #pragma unroll
  for (int r=0;r<8;r++){
    int gr = rb + ty*8 + r;
    #pragma unroll
    for (int u=0;u<8;u++){
      int gc = cb + tx*8 + u;
      g_xproj[gr*512 + gc] = acc[r][u] + g_bsum[0][gc];
    }
  }
}

// ---- fused LSTM step: gates GEMM + pointwise update ----
// Block: 128 rows x 32 n (x4 gates, interleaved col = n_local*4 + gate)
template<int LAYER>
__global__ __launch_bounds__(256) void k_step(const float* __restrict__ Wh,
                                              const float* __restrict__ Wi,
                                              int t){
  __shared__ __align__(16) float As[32][132];
  __shared__ __align__(16) float Bs[32][132];
  int tid = threadIdx.x, tx = tid & 15, ty = tid >> 4;
  int rb = blockIdx.x*128, n0 = blockIdx.y*32;
  int rp = t & 1, wp = rp ^ 1;
  const float* Hst = g_h[LAYER][rp];
  float acc[8][8] = {};

  for (int kc=0; kc<128; kc+=32){
    for (int i=tid;i<4096;i+=256){
      int r = i>>5, kk = i&31;
      As[kk][r] = Hst[(rb+r)*NHn + kc + kk];
    }
    for (int i=tid;i<4096;i+=256){
      int c = i>>5, kk = i&31;
      int wrow = ((c&3)<<7) + n0 + (c>>2);
      Bs[kk][c] = Wh[wrow*NHn + kc + kk];
    }
    __syncthreads();
    GEMM_CHUNK(As,Bs,acc,tx,ty);
    __syncthreads();
  }
  if (LAYER == 1){
    const float* Hp = &g_hseq[t][0];
    for (int kc=0; kc<128; kc+=32){
      for (int i=tid;i<4096;i+=256){
        int r = i>>5, kk = i&31;
        As[kk][r] = Hp[(rb+r)*NHn + kc + kk];
      }
      for (int i=tid;i<4096;i+=256){
        int c = i>>5, kk = i&31;
        int wrow = ((c&3)<<7) + n0 + (c>>2);
        Bs[kk][c] = Wi[wrow*NHn + kc + kk];
      }
      __syncthreads();
      GEMM_CHUNK(As,Bs,acc,tx,ty);
      __syncthreads();
    }
  }
  // epilogue: i,f,g,o -> c,h
  #pragma unroll
  for (int r=0;r<8;r++){
    int row = rb + ty*8 + r;
    int b = row & 63;
    const float* add = (LAYER==0) ? &g_xproj[(t*64+b)*512] : &g_bsum[1][0];
    #pragma unroll
    for (int p=0;p<2;p++){
      int n = n0 + tx*2 + p;
      float gi = acc[r][p*4+0] + add[      n];
      float gf = acc[r][p*4+1] + add[128 + n];
      float gg = acc[r][p*4+2] + add[256 + n];
      float go = acc[r][p*4+3] + add[384 + n];
      float cold = g_c[LAYER][row*NHn + n];
      float cn = sigm(gf)*cold + sigm(gi)*tanhf(gg);
      float hn = sigm(go)*tanhf(cn);
      g_c[LAYER][row*NHn + n] = cn;
      g_h[LAYER][wp][row*NHn + n] = hn;
      if (LAYER == 0) g_hseq[t][row*NHn + n] = hn;
    }
  }
}

// ---- uhi_pred + anomalies A ----
__global__ void k_up(const float* __restrict__ nh, const float* __restrict__ nc,
                     const float* qp, const float* ep){
  int m = blockIdx.x;                      // (l*64+b)*128 + n, 16384
  int j = threadIdx.x;                     // ensemble col 0..127
  int n = m & 127, b = (m>>7)&63, l = m>>13;
  float q = fabsf(*qp), e = fabsf(*ep);
  float v;
  if (j < 64)
    v = g_h[l][0][(j*64+b)*NHn + n] + q * nh[((j*LSn + l)*BSn + b)*NHn + n];
  else {
    int j2 = j - 64;
    v = g_c[l][(j2*64+b)*NHn + n] + e * nc[((j2*LSn + l)*BSn + b)*NHn + n];
  }
  __shared__ float red[128];
  red[j] = v; __syncthreads();
  for (int s=64;s>0;s>>=1){ if (j<s) red[j]+=red[j+s]; __syncthreads(); }
  float mean = red[0]*(1.f/128.f);
  g_up[(long)m*128 + j] = v;
  g_Am[(long)m*128 + j] = v - mean;
}

// ---- hxi, HA, innov ----
__global__ void k_hxi(const float* __restrict__ Hm, const float* __restrict__ y){
  int b = blockIdx.x, N = threadIdx.x;
  __shared__ float Hs[128];
  Hs[N] = Hm[N]; __syncthreads();
  float s = 0.f;
  for (int n=0;n<128;n++) s += g_up[((long)(b*128+n))*128 + N] * Hs[n];
  __shared__ float red[128];
  red[N] = s; __syncthreads();
  for (int st=64;st>0;st>>=1){ if (N<st) red[N]+=red[N+st]; __syncthreads(); }
  float mean = red[0]*(1.f/128.f);
  g_HA[b*128+N] = s - mean;
  g_innov[b*128+N] = y[b] - s;
}

__global__ void k_P(const float* rp){
  int c = blockIdx.x, d = threadIdx.x;
  float s = 0.f;
  for (int N=0;N<128;N++) s += g_HA[c*128+N]*g_HA[d*128+N];
  float r = *rp;
  g_P[c*64+d] = s*(1.f/127.f) + (c==d ? r*r : 0.f);
}

// ---- Gauss-Jordan inverse of P (64x64), one block, 128 threads ----
__global__ void k_inv(){
  __shared__ float M[64][128];
  __shared__ float fcol[64];
  __shared__ int spiv;
  int tid = threadIdx.x;
  for (int e=tid;e<8192;e+=128){
    int r = e>>7, c = e&127;
    M[r][c] = (c<64) ? g_P[r*64+c] : ((c-64)==r ? 1.f : 0.f);
  }
  __syncthreads();
  for (int k=0;k<64;k++){
    if (tid==0){
      int p = k; float best = fabsf(M[k][k]);
      for (int rr=k+1;rr<64;rr++){ float v=fabsf(M[rr][k]); if (v>best){best=v;p=rr;} }
      spiv = p;
    }
    __syncthreads();
    int p = spiv;
    if (p != k){ float tmp = M[k][tid]; M[k][tid] = M[p][tid]; M[p][tid] = tmp; }
    __syncthreads();
    float pv = M[k][k];
    __syncthreads();
    M[k][tid] = M[k][tid] / pv;
    __syncthreads();
    if (tid < 64) fcol[tid] = M[tid][k];
    __syncthreads();
    for (int e=tid;e<8192;e+=128){
      int r = e>>7, c = e&127;
      if (r != k) M[r][c] -= fcol[r]*M[k][c];
    }
    __syncthreads();
  }
  for (int e=tid;e<4096;e+=128){
    int r = e>>6, d = e&63;
    g_Pinv[r*64+d] = M[r][64+d];
  }
}

__global__ void k_T2(){
  int c = blockIdx.x, M = threadIdx.x;
  float s = 0.f;
  for (int d=0;d<64;d++) s += g_Pinv[c*64+d]*g_innov[d*128+M];
  g_T2[c*128+M] = s;
}

__global__ void k_T1(){
  int N = blockIdx.x, M = threadIdx.x;
  __shared__ float HAc[64];
  if (M < 64) HAc[M] = g_HA[M*128 + N];
  __syncthreads();
  float s = 0.f;
  for (int c=0;c<64;c++) s += HAc[c]*g_T2[c*128+M];
  g_T1[N*128+M] = s;
}

// ---- X_new = up + A@T1/127, one block per (l,b) ----
__global__ __launch_bounds__(256) void k_upd(float* __restrict__ out){
  __shared__ __align__(16) float As[32][132];
  __shared__ __align__(16) float Bs[32][132];
  int lb = blockIdx.x;
  int tid = threadIdx.x, tx = tid & 15, ty = tid >> 4;
  const float* Ab = &g_Am[(long)lb*16384];
  float acc[8][8] = {};
  for (int kc=0; kc<128; kc+=32){
    for (int i=tid;i<4096;i+=256){
      int r = i>>5, kk = i&31;
      As[kk][r] = Ab[r*128 + kc + kk];
    }
    for (int i=tid;i<4096;i+=256){
      int c = i&127, kk = i>>7;
      Bs[kk][c] = g_T1[(kc+kk)*128 + c];
    }
    __syncthreads();
    GEMM_CHUNK(As,Bs,acc,tx,ty);
    __syncthreads();
  }
  #pragma unroll
  for (int r=0;r<8;r++){
    int n = ty*8 + r;
    #pragma unroll
    for (int u=0;u<8;u++){
      int Mc = tx*8 + u;
      long idx = (long)lb*16384 + n*128 + Mc;
      out[OUT_X + idx] = g_up[idx] + acc[r][u]*(1.f/127.f);
    }
  }
}

__global__ void k_rmean(const float* __restrict__ out){
  int row = blockIdx.x;                 // (l*64+b)*128 + n
  int M = threadIdx.x;
  float v = out[OUT_X + (long)row*128 + M];
  __shared__ float red[128];
  red[M] = v; __syncthreads();
  for (int s=64;s>0;s>>=1){ if (M<s) red[M]+=red[M+s]; __syncthreads(); }
  if (M==0) g_rmean[row] = red[0]*(1.f/128.f);
}

// ---- Cov_new = An@An^T/127, one block per (l,b) ----
__global__ __launch_bounds__(256) void k_cov(float* __restrict__ out){
  __shared__ __align__(16) float S[32][132];
  int lb = blockIdx.x;
  int tid = threadIdx.x, tx = tid & 15, ty = tid >> 4;
  const float* Xb = out + OUT_X + (long)lb*16384;
  const float* mu = &g_rmean[lb*128];
  float acc[8][8] = {};
  for (int kc=0; kc<128; kc+=32){
    for (int i=tid;i<4096;i+=256){
      int r = i>>5, kk = i&31;
      S[kk][r] = Xb[r*128 + kc + kk] - mu[r];
    }
    __syncthreads();
    GEMM_CHUNK(S,S,acc,tx,ty);
    __syncthreads();
  }
  #pragma unroll
  for (int r=0;r<8;r++){
    int n = ty*8 + r;
    #pragma unroll
    for (int u=0;u<8;u++){
      int m = tx*8 + u;
      out[OUT_COV + (long)lb*16384 + n*128 + m] = acc[r][u]*(1.f/127.f);
    }
  }
}

__global__ void k_Y(const float* __restrict__ Hm, float* __restrict__ out){
  int b = blockIdx.x, N = threadIdx.x;
  __shared__ float Hs[128];
  Hs[N] = Hm[N]; __syncthreads();
  float s = 0.f;
  for (int n=0;n<128;n++) s += out[OUT_X + (long)b*16384 + n*128 + N] * Hs[n];
  __shared__ float red[128];
  red[N] = s; __syncthreads();
  for (int st=64;st>0;st>>=1){ if (N<st) red[N]+=red[N+st]; __syncthreads(); }
  float mean = red[0]*(1.f/128.f);
  g_AY[b*128+N] = s - mean;
  if (N==0){ g_fout[b] = mean; out[OUT_FO + b] = mean; }
}

__global__ void k_fcov(const float* rp, float* __restrict__ out){
  int c = blockIdx.x, d = threadIdx.x;
  float s = 0.f;
  for (int N=0;N<128;N++) s += g_AY[c*128+N]*g_AY[d*128+N];
  float r = *rp;
  float v = s*(1.f/127.f) + (c==d ? r*r : 0.f);
  g_fcov[c*64+d] = v;
  out[OUT_FCOV + c*64+d] = v;
}

// ---- Cholesky + logdet + solve -> ll ----
__global__ void k_ll(const float* __restrict__ y, float* __restrict__ out){
  __shared__ float A[64][65];
  __shared__ float red[64];
  int tid = threadIdx.x;
  for (int c=0;c<64;c++) A[tid][c] = g_fcov[tid*64+c];
  __syncthreads();
  for (int k=0;k<64;k++){
    if (tid==k) A[k][k] = sqrtf(A[k][k]);
    __syncthreads();
    float lkk = A[k][k];
    if (tid>k) A[tid][k] /= lkk;
    __syncthreads();
    if (tid>k){
      float lrk = A[tid][k];
      for (int c=k+1;c<=tid;c++) A[tid][c] -= lrk*A[c][k];
    }
    __syncthreads();
  }
  red[tid] = 2.f*logf(A[tid][tid]);
  __syncthreads();
  for (int s=32;s>0;s>>=1){ if (tid<s) red[tid]+=red[tid+s]; __syncthreads(); }
  if (tid==0){
    float logdet = red[0];
    float z[64];
    for (int k=0;k<64;k++){
      float s = y[k] - g_fout[k];
      for (int j=0;j<k;j++) s -= A[k][j]*z[j];
      z[k] = s / A[k][k];
    }
    float qs = 0.f;
    for (int k=0;k<64;k++) qs += z[k]*z[k];
    out[OUT_LL] = -0.5f*logdet - 0.5f*qs;
  }
}

extern "C" void kernel_launch(void* const* d_in, const int* in_sizes, int n_in,
                              void* d_out, int out_size){
  const float* x    = (const float*)d_in[0];
  const float* y    = (const float*)d_in[1];
  const float* uhi  = (const float*)d_in[2];
  const float* W_ih = (const float*)d_in[3];
  const float* W_hh = (const float*)d_in[4];
  const float* b_ih = (const float*)d_in[5];
  const float* b_hh = (const float*)d_in[6];
  const float* Hm   = (const float*)d_in[7];
  const float* q    = (const float*)d_in[8];
  const float* e    = (const float*)d_in[9];
  const float* r    = (const float*)d_in[10];
  const float* nh   = (const float*)d_in[11];
  const float* nc   = (const float*)d_in[12];
  float* out = (float*)d_out;

  k_init<<<4096, 256>>>(uhi);
  k_bias<<<4, 256>>>(b_ih, b_hh);
  dim3 gproj(32, 4);
  k_xproj<<<gproj, 256>>>(x, W_ih);            // layer 0 input projection (+biases)

  dim3 gs(32, 4);
  for (int t=0; t<Tn; t++)
    k_step<0><<<gs, 256>>>(W_hh, W_ih, t);
  for (int t=0; t<Tn; t++)
    k_step<1><<<gs, 256>>>(W_hh + 512*128, W_ih + 512*128, t);

  k_up<<<16384, 128>>>(nh, nc, q, e);
  k_hxi<<<64, 128>>>(Hm, y);
  k_P<<<64, 64>>>(r);
  k_inv<<<1, 128>>>();
  k_T2<<<64, 128>>>();
  k_T1<<<128, 128>>>();
  k_upd<<<128, 256>>>(out);
  k_rmean<<<16384, 128>>>(out);
  k_cov<<<128, 256>>>(out);
  k_Y<<<64, 128>>>(Hm, out);
  k_fcov<<<64, 64>>>(r, out);
  k_ll<<<1, 64>>>(y, out);
}

// round 4
// speedup vs baseline: 1.8882x; 1.8870x over previous
#include <cuda_runtime.h>
#include <cuda_bf16.h>
#include <cstdint>
#include <math.h>

#define LSn 2
#define BSn 64
#define Tn 64
#define NHn 128
#define HW (4096*128)
#define OUT_FO   0
#define OUT_FCOV 64
#define OUT_X    4160
#define OUT_COV  2101312
#define OUT_LL   4198464

// ---------------- device scratch ----------------
__device__ __align__(256) __nv_bfloat16 g_hbhi[2][2][HW];
__device__ __align__(256) __nv_bfloat16 g_hblo[2][2][HW];
__device__ __align__(256) __nv_bfloat16 g_sqhi[Tn][HW];
__device__ __align__(256) __nv_bfloat16 g_sqlo[Tn][HW];
__device__ __align__(256) __nv_bfloat16 g_Whhi[2][512*128];
__device__ __align__(256) __nv_bfloat16 g_Whlo[2][512*128];
__device__ __align__(256) __nv_bfloat16 g_Wihi[512*128];
__device__ __align__(256) __nv_bfloat16 g_Wilo[512*128];
__device__ float g_c0[2][HW];
__device__ float g_hT[2][HW];
__device__ float g_cT[2][HW];
__device__ float g_xproj[Tn*512*64];     // [(t*512+gc)*64+b]
__device__ float g_bsum[2][512];
__device__ unsigned g_gcnt[32];
__device__ unsigned g_ggen[32];

__device__ float g_up[2*64*128*128];
__device__ float g_Am[2*64*128*128];
__device__ float g_HA[64*128];
__device__ float g_innov[64*128];
__device__ float g_P[64*64];
__device__ float g_Pinv[64*64];
__device__ float g_T2[64*128];
__device__ float g_T1[128*128];
__device__ float g_rmean[2*64*128];
__device__ float g_AY[64*128];
__device__ float g_fout[64];
__device__ float g_fcov[64*64];

__device__ __forceinline__ float sigm(float x){ return 1.f/(1.f + __expf(-x)); }

#define SROW 272   // padded row stride in bytes (136 bf16)

#define MMA_BF16(d, a, b0_, b1_) \
  asm volatile("mma.sync.aligned.m16n8k16.row.col.f32.bf16.bf16.f32 " \
    "{%0,%1,%2,%3},{%4,%5,%6,%7},{%8,%9},{%0,%1,%2,%3};" \
    : "+f"((d)[0]),"+f"((d)[1]),"+f"((d)[2]),"+f"((d)[3]) \
    : "r"((a)[0]),"r"((a)[1]),"r"((a)[2]),"r"((a)[3]),"r"(b0_),"r"(b1_))

__device__ __forceinline__ void st16(__nv_bfloat16* p, __nv_bfloat16 v){
  unsigned short u = __bfloat16_as_ushort(v);
  asm volatile("st.global.u16 [%0], %1;" :: "l"(p), "h"(u) : "memory");
}

// 128x128 bf16 row-major gmem -> smem rows padded to 272B
__device__ __forceinline__ void cp_tile(const __nv_bfloat16* __restrict__ src, char* dst, int tid){
  const uint4* s4 = (const uint4*)src;
  #pragma unroll
  for (int it=0; it<8; it++){
    int i = it*256 + tid;            // 0..2047
    uint4 v = __ldcg(&s4[i]);
    int row = i>>4, ck = i&15;
    *(uint4*)(dst + row*SROW + ck*16) = v;
  }
}

__device__ __forceinline__ void group_bar(int rt, int tid){
  __syncthreads();
  if (tid==0){
    __threadfence();
    unsigned gen = *(volatile unsigned*)&g_ggen[rt];
    if (atomicInc(&g_gcnt[rt], 3u) == 3u){
      *(volatile unsigned*)&g_ggen[rt] = gen + 1u;
    } else {
      while (*(volatile unsigned*)&g_ggen[rt] == gen) __nanosleep(32);
    }
    __threadfence();
  }
  __syncthreads();
}

__device__ __forceinline__ void gemm_phase(float acc[8][2][4],
                                           const char* sAh, const char* sAl,
                                           const char* sBh, const char* sBl,
                                           int g, int tg, int wm, int wn){
  #pragma unroll
  for (int kc=0; kc<8; kc++){
    int kb = (kc*16 + 2*tg)*2;
    uint32_t ah[2][4], al[2][4];
    #pragma unroll
    for (int im=0; im<2; im++){
      int rA = (wm*32 + im*16 + g)*SROW + kb;
      ah[im][0] = *(const uint32_t*)(sAh + rA);
      ah[im][1] = *(const uint32_t*)(sAh + rA + 8*SROW);
      ah[im][2] = *(const uint32_t*)(sAh + rA + 16);
      ah[im][3] = *(const uint32_t*)(sAh + rA + 8*SROW + 16);
      al[im][0] = *(const uint32_t*)(sAl + rA);
      al[im][1] = *(const uint32_t*)(sAl + rA + 8*SROW);
      al[im][2] = *(const uint32_t*)(sAl + rA + 16);
      al[im][3] = *(const uint32_t*)(sAl + rA + 8*SROW + 16);
    }
    #pragma unroll
    for (int in=0; in<8; in++){
      int boff = (wn*64 + in*8 + g)*SROW + kb;
      uint32_t bh0 = *(const uint32_t*)(sBh + boff);
      uint32_t bh1 = *(const uint32_t*)(sBh + boff + 16);
      uint32_t bl0 = *(const uint32_t*)(sBl + boff);
      uint32_t bl1 = *(const uint32_t*)(sBl + boff + 16);
      #pragma unroll
      for (int im=0; im<2; im++){
        MMA_BF16(acc[in][im], ah[im], bh0, bh1);
        MMA_BF16(acc[in][im], ah[im], bl0, bl1);
        MMA_BF16(acc[in][im], al[im], bh0, bh1);
      }
    }
  }
}

// ---------------- prep ----------------
__global__ void k_init(const float* __restrict__ uhi){
  int idx = blockIdx.x*blockDim.x + threadIdx.x;
  int k = idx & 127, b = (idx>>7)&63, j = (idx>>13)&63, l = idx>>19;
  long base = (((long)(l*BSn+b))*NHn + k)*128;
  float h0 = uhi[base + j];
  int row = j*64+b;
  __nv_bfloat16 hi = __float2bfloat16(h0);
  g_hbhi[l][0][row*128+k] = hi;
  g_hblo[l][0][row*128+k] = __float2bfloat16(h0 - __bfloat162float(hi));
  g_c0[l][row*128+k] = uhi[base + 64 + j];
  if (idx < 32){ g_gcnt[idx] = 0; g_ggen[idx] = 0; }
}

__global__ void k_bias(const float* __restrict__ bih, const float* __restrict__ bhh){
  int idx = blockIdx.x*blockDim.x + threadIdx.x;
  if (idx < 1024) g_bsum[idx>>9][idx&511] = bih[idx] + bhh[idx];
}

// weight split: tile-local col c of col-tile ct -> natural row (c&3)*128 + ct*32 + (c>>2)
__global__ void k_prep(const float* __restrict__ W_ih, const float* __restrict__ W_hh){
  int idx = blockIdx.x*blockDim.x + threadIdx.x;   // 131072
  int k = idx & 127, cg = (idx>>7)&511, l = idx>>16;
  int ct = cg>>7, c = cg&127;
  int nat = (c&3)*128 + ct*32 + (c>>2);
  float wh = W_hh[l*65536 + nat*128 + k];
  __nv_bfloat16 hhi = __float2bfloat16(wh);
  g_Whhi[l][cg*128+k] = hhi;
  g_Whlo[l][cg*128+k] = __float2bfloat16(wh - __bfloat162float(hhi));
  if (l==1){
    float wi = W_ih[65536 + nat*128 + k];
    __nv_bfloat16 ihi = __float2bfloat16(wi);
    g_Wihi[cg*128+k] = ihi;
    g_Wilo[cg*128+k] = __float2bfloat16(wi - __bfloat162float(ihi));
  }
}

#define GEMM_CHUNK(AS,BS_,ACC,TX,TY)                                   \
  _Pragma("unroll 4")                                                  \
  for (int k2=0;k2<32;k2++){                                           \
    float a_[8], b_[8];                                                \
    *(float4*)&a_[0] = *(const float4*)&AS[k2][(TY)*8];                \
    *(float4*)&a_[4] = *(const float4*)&AS[k2][(TY)*8+4];              \
    *(float4*)&b_[0] = *(const float4*)&BS_[k2][(TX)*8];               \
    *(float4*)&b_[4] = *(const float4*)&BS_[k2][(TX)*8+4];             \
    _Pragma("unroll")                                                  \
    for (int ii=0;ii<8;ii++){                                          \
      _Pragma("unroll")                                                \
      for (int jj=0;jj<8;jj++) ACC[ii][jj] += a_[ii]*b_[jj];           \
    }                                                                  \
  }

__global__ __launch_bounds__(256) void k_xproj(const float* __restrict__ x,
                                               const float* __restrict__ Wi0){
  __shared__ __align__(16) float As[32][132];
  __shared__ __align__(16) float Bs[32][132];
  int tid = threadIdx.x, tx = tid & 15, ty = tid >> 4;
  int rb = blockIdx.x*128, cb = blockIdx.y*128;
  float acc[8][8] = {};
  for (int kc=0; kc<128; kc+=32){
    for (int i=tid;i<4096;i+=256){
      int r = i>>5, kk = i&31;
      int gr = rb + r, b = gr & 63, t = gr >> 6;
      As[kk][r] = x[(b*Tn + t)*128 + kc + kk];
    }
    for (int i=tid;i<4096;i+=256){
      int c = i>>5, kk = i&31;
      Bs[kk][c] = Wi0[(cb + c)*128 + kc + kk];
    }
    __syncthreads();
    GEMM_CHUNK(As,Bs,acc,tx,ty);
    __syncthreads();
  }
  #pragma unroll
  for (int r=0;r<8;r++){
    int gr = rb + ty*8 + r, b = gr & 63, t = gr >> 6;
    #pragma unroll
    for (int u=0;u<8;u++){
      int gc = cb + tx*8 + u;
      g_xproj[((long)t*512 + gc)*64 + b] = acc[r][u] + g_bsum[0][gc];
    }
  }
}

// ---------------- persistent HMMA LSTM ----------------
// smem: A_hi(34816) A_lo(34816) W0 W1 W2 W3 (34816 each) = 208896 bytes
#define SM_AH 0
#define SM_AL 34816
#define SM_W0 69632
#define SM_W1 104448
#define SM_W2 139264
#define SM_W3 174080
#define SMEM_SZ 208896

__global__ __launch_bounds__(256,1) void k_lstm(){
  extern __shared__ __align__(16) char smem[];
  char* sAh = smem + SM_AH;  char* sAl = smem + SM_AL;
  char* sW0 = smem + SM_W0;  char* sW1 = smem + SM_W1;
  char* sW2 = smem + SM_W2;  char* sW3 = smem + SM_W3;
  int tid = threadIdx.x, wid = tid>>5, lane = tid&31;
  int g = lane>>2, tg = lane&3;
  int wm = wid&3, wn = wid>>2;
  int rt = blockIdx.x>>2, ct = blockIdx.x&3;
  int s = tg&1, csel = tg>>1;
  int rowbase = rt*128 + wm*32 + g + 8*s;   // + im*16
  int nbase   = ct*32 + wn*16 + csel;       // + in*2
  int src_if = (g<<2) + (csel<<1);
  int src_go = src_if + 1;
  float creg[16];

  for (int l=0; l<2; l++){
    cp_tile(&g_Whhi[l][ct*16384], sW0, tid);
    cp_tile(&g_Whlo[l][ct*16384], sW1, tid);
    if (l==1){
      cp_tile(&g_Wihi[ct*16384], sW2, tid);
      cp_tile(&g_Wilo[ct*16384], sW3, tid);
    }
    #pragma unroll
    for (int im=0; im<2; im++)
      #pragma unroll
      for (int in=0; in<8; in++)
        creg[im*8+in] = g_c0[l][(long)(rowbase+im*16)*128 + nbase + in*2];
    __syncthreads();

    for (int t=0; t<64; t++){
      int rp = t&1, wp = rp^1;
      cp_tile(&g_hbhi[l][rp][rt*16384], sAh, tid);
      cp_tile(&g_hblo[l][rp][rt*16384], sAl, tid);
      __syncthreads();
      float acc[8][2][4];
      #pragma unroll
      for (int in=0;in<8;in++)
        #pragma unroll
        for (int im=0;im<2;im++)
          #pragma unroll
          for (int r=0;r<4;r++) acc[in][im][r] = 0.f;
      gemm_phase(acc, sAh, sAl, sW0, sW1, g, tg, wm, wn);
      if (l==1){
        __syncthreads();
        cp_tile(&g_sqhi[t][rt*16384], sAh, tid);
        cp_tile(&g_sqlo[t][rt*16384], sAl, tid);
        __syncthreads();
        gemm_phase(acc, sAh, sAl, sW2, sW3, g, tg, wm, wn);
      }

      const float* xp = g_xproj + (long)t*32768;
      #pragma unroll
      for (int im=0; im<2; im++){
        int row = rowbase + im*16;
        int b = row & 63;
        #pragma unroll
        for (int in=0; in<8; in++){
          float* A4 = acc[in][im];
          float v0 = __shfl_sync(0xFFFFFFFFu, A4[0], src_if);
          float v2 = __shfl_sync(0xFFFFFFFFu, A4[2], src_if);
          float v1 = __shfl_sync(0xFFFFFFFFu, A4[1], src_if);
          float v3 = __shfl_sync(0xFFFFFFFFu, A4[3], src_if);
          float w0 = __shfl_sync(0xFFFFFFFFu, A4[0], src_go);
          float w2 = __shfl_sync(0xFFFFFFFFu, A4[2], src_go);
          float w1 = __shfl_sync(0xFFFFFFFFu, A4[1], src_go);
          float w3 = __shfl_sync(0xFFFFFFFFu, A4[3], src_go);
          float gi = s ? v2 : v0;
          float gf = s ? v3 : v1;
          float gg = s ? w2 : w0;
          float go_ = s ? w3 : w1;
          int n = nbase + in*2;
          if (l==0){
            gi += xp[(      n)*64 + b];
            gf += xp[(128 + n)*64 + b];
            gg += xp[(256 + n)*64 + b];
            go_ += xp[(384 + n)*64 + b];
          } else {
            gi += g_bsum[1][      n];
            gf += g_bsum[1][128 + n];
            gg += g_bsum[1][256 + n];
            go_ += g_bsum[1][384 + n];
          }
          int idx = im*8 + in;
          float cc = sigm(gf)*creg[idx] + sigm(gi)*tanhf(gg);
          creg[idx] = cc;
          float hv = sigm(go_)*tanhf(cc);
          __nv_bfloat16 bh = __float2bfloat16(hv);
          __nv_bfloat16 blo = __float2bfloat16(hv - __bfloat162float(bh));
          long off = (long)row*128 + n;
          st16(&g_hbhi[l][wp][off], bh);
          st16(&g_hblo[l][wp][off], blo);
          if (l==0){
            st16(&g_sqhi[t][off], bh);
            st16(&g_sqlo[t][off], blo);
          }
          if (t==63){
            g_hT[l][off] = hv;
            g_cT[l][off] = cc;
          }
        }
      }
      group_bar(rt, tid);
    }
  }
}

// ---------------- EnKF tail ----------------
__global__ void k_up(const float* __restrict__ nh, const float* __restrict__ nc,
                     const float* qp, const float* ep){
  int m = blockIdx.x;
  int j = threadIdx.x;
  int n = m & 127, b = (m>>7)&63, l = m>>13;
  float q = fabsf(*qp), e = fabsf(*ep);
  float v;
  if (j < 64)
    v = g_hT[l][(j*64+b)*128 + n] + q * nh[((j*LSn + l)*BSn + b)*128 + n];
  else {
    int j2 = j - 64;
    v = g_cT[l][(j2*64+b)*128 + n] + e * nc[((j2*LSn + l)*BSn + b)*128 + n];
  }
  __shared__ float red[128];
  red[j] = v; __syncthreads();
  for (int st=64;st>0;st>>=1){ if (j<st) red[j]+=red[j+st]; __syncthreads(); }
  float mean = red[0]*(1.f/128.f);
  g_up[(long)m*128 + j] = v;
  g_Am[(long)m*128 + j] = v - mean;
}

__global__ void k_hxi(const float* __restrict__ Hm, const float* __restrict__ y){
  int b = blockIdx.x, N = threadIdx.x;
  __shared__ float Hs[128];
  Hs[N] = Hm[N]; __syncthreads();
  float sm = 0.f;
  for (int n=0;n<128;n++) sm += g_up[((long)(b*128+n))*128 + N] * Hs[n];
  __shared__ float red[128];
  red[N] = sm; __syncthreads();
  for (int st=64;st>0;st>>=1){ if (N<st) red[N]+=red[N+st]; __syncthreads(); }
  float mean = red[0]*(1.f/128.f);
  g_HA[b*128+N] = sm - mean;
  g_innov[b*128+N] = y[b] - sm;
}

__global__ void k_P(const float* rp){
  int c = blockIdx.x, d = threadIdx.x;
  float sm = 0.f;
  for (int N=0;N<128;N++) sm += g_HA[c*128+N]*g_HA[d*128+N];
  float r = *rp;
  g_P[c*64+d] = sm*(1.f/127.f) + (c==d ? r*r : 0.f);
}

__global__ void k_inv(){
  __shared__ float M[64][128];
  __shared__ float fcol[64];
  __shared__ int spiv;
  int tid = threadIdx.x;
  for (int e=tid;e<8192;e+=128){
    int r = e>>7, c = e&127;
    M[r][c] = (c<64) ? g_P[r*64+c] : ((c-64)==r ? 1.f : 0.f);
  }
  __syncthreads();
  for (int k=0;k<64;k++){
    if (tid==0){
      int p = k; float best = fabsf(M[k][k]);
      for (int rr=k+1;rr<64;rr++){ float v=fabsf(M[rr][k]); if (v>best){best=v;p=rr;} }
      spiv = p;
    }
    __syncthreads();
    int p = spiv;
    if (p != k){ float tmp = M[k][tid]; M[k][tid] = M[p][tid]; M[p][tid] = tmp; }
    __syncthreads();
    float pv = M[k][k];
    __syncthreads();
    M[k][tid] = M[k][tid] / pv;
    __syncthreads();
    if (tid < 64) fcol[tid] = M[tid][k];
    __syncthreads();
    for (int e=tid;e<8192;e+=128){
      int r = e>>7, c = e&127;
      if (r != k) M[r][c] -= fcol[r]*M[k][c];
    }
    __syncthreads();
  }
  for (int e=tid;e<4096;e+=128){
    int r = e>>6, d = e&63;
    g_Pinv[r*64+d] = M[r][64+d];
  }
}

__global__ void k_T2(){
  int c = blockIdx.x, M = threadIdx.x;
  float sm = 0.f;
  for (int d=0;d<64;d++) sm += g_Pinv[c*64+d]*g_innov[d*128+M];
  g_T2[c*128+M] = sm;
}

__global__ void k_T1(){
  int N = blockIdx.x, M = threadIdx.x;
  __shared__ float HAc[64];
  if (M < 64) HAc[M] = g_HA[M*128 + N];
  __syncthreads();
  float sm = 0.f;
  for (int c=0;c<64;c++) sm += HAc[c]*g_T2[c*128+M];
  g_T1[N*128+M] = sm;
}

__global__ __launch_bounds__(256) void k_upd(float* __restrict__ out){
  __shared__ __align__(16) float As[32][132];
  __shared__ __align__(16) float Bs[32][132];
  int lb = blockIdx.x;
  int tid = threadIdx.x, tx = tid & 15, ty = tid >> 4;
  const float* Ab = &g_Am[(long)lb*16384];
  float acc[8][8] = {};
  for (int kc=0; kc<128; kc+=32){
    for (int i=tid;i<4096;i+=256){
      int r = i>>5, kk = i&31;
      As[kk][r] = Ab[r*128 + kc + kk];
    }
    for (int i=tid;i<4096;i+=256){
      int c = i&127, kk = i>>7;
      Bs[kk][c] = g_T1[(kc+kk)*128 + c];
    }
    __syncthreads();
    GEMM_CHUNK(As,Bs,acc,tx,ty);
    __syncthreads();
  }
  #pragma unroll
  for (int r=0;r<8;r++){
    int n = ty*8 + r;
    #pragma unroll
    for (int u=0;u<8;u++){
      int Mc = tx*8 + u;
      long idx = (long)lb*16384 + n*128 + Mc;
      out[OUT_X + idx] = g_up[idx] + acc[r][u]*(1.f/127.f);
    }
  }
}

__global__ void k_rmean(const float* __restrict__ out){
  int row = blockIdx.x;
  int M = threadIdx.x;
  float v = out[OUT_X + (long)row*128 + M];
  __shared__ float red[128];
  red[M] = v; __syncthreads();
  for (int st=64;st>0;st>>=1){ if (M<st) red[M]+=red[M+st]; __syncthreads(); }
  if (M==0) g_rmean[row] = red[0]*(1.f/128.f);
}

__global__ __launch_bounds__(256) void k_cov(float* __restrict__ out){
  __shared__ __align__(16) float S[32][132];
  int lb = blockIdx.x;
  int tid = threadIdx.x, tx = tid & 15, ty = tid >> 4;
  const float* Xb = out + OUT_X + (long)lb*16384;
  const float* mu = &g_rmean[lb*128];
  float acc[8][8] = {};
  for (int kc=0; kc<128; kc+=32){
    for (int i=tid;i<4096;i+=256){
      int r = i>>5, kk = i&31;
      S[kk][r] = Xb[r*128 + kc + kk] - mu[r];
    }
    __syncthreads();
    GEMM_CHUNK(S,S,acc,tx,ty);
    __syncthreads();
  }
  #pragma unroll
  for (int r=0;r<8;r++){
    int n = ty*8 + r;
    #pragma unroll
    for (int u=0;u<8;u++){
      int m = tx*8 + u;
      out[OUT_COV + (long)lb*16384 + n*128 + m] = acc[r][u]*(1.f/127.f);
    }
  }
}

__global__ void k_Y(const float* __restrict__ Hm, float* __restrict__ out){
  int b = blockIdx.x, N = threadIdx.x;
  __shared__ float Hs[128];
  Hs[N] = Hm[N]; __syncthreads();
  float sm = 0.f;
  for (int n=0;n<128;n++) sm += out[OUT_X + (long)b*16384 + n*128 + N] * Hs[n];
  __shared__ float red[128];
  red[N] = sm; __syncthreads();
  for (int st=64;st>0;st>>=1){ if (N<st) red[N]+=red[N+st]; __syncthreads(); }
  float mean = red[0]*(1.f/128.f);
  g_AY[b*128+N] = sm - mean;
  if (N==0){ g_fout[b] = mean; out[OUT_FO + b] = mean; }
}

__global__ void k_fcov(const float* rp, float* __restrict__ out){
  int c = blockIdx.x, d = threadIdx.x;
  float sm = 0.f;
  for (int N=0;N<128;N++) sm += g_AY[c*128+N]*g_AY[d*128+N];
  float r = *rp;
  float v = sm*(1.f/127.f) + (c==d ? r*r : 0.f);
  g_fcov[c*64+d] = v;
  out[OUT_FCOV + c*64+d] = v;
}

__global__ void k_ll(const float* __restrict__ y, float* __restrict__ out){
  __shared__ float A[64][65];
  __shared__ float red[64];
  int tid = threadIdx.x;
  for (int c=0;c<64;c++) A[tid][c] = g_fcov[tid*64+c];
  __syncthreads();
  for (int k=0;k<64;k++){
    if (tid==k) A[k][k] = sqrtf(A[k][k]);
    __syncthreads();
    float lkk = A[k][k];
    if (tid>k) A[tid][k] /= lkk;
    __syncthreads();
    if (tid>k){
      float lrk = A[tid][k];
      for (int c=k+1;c<=tid;c++) A[tid][c] -= lrk*A[c][k];
    }
    __syncthreads();
  }
  red[tid] = 2.f*logf(A[tid][tid]);
  __syncthreads();
  for (int st=32;st>0;st>>=1){ if (tid<st) red[tid]+=red[tid+st]; __syncthreads(); }
  if (tid==0){
    float logdet = red[0];
    float z[64];
    for (int k=0;k<64;k++){
      float sm = y[k] - g_fout[k];
      for (int j=0;j<k;j++) sm -= A[k][j]*z[j];
      z[k] = sm / A[k][k];
    }
    float qs = 0.f;
    for (int k=0;k<64;k++) qs += z[k]*z[k];
    out[OUT_LL] = -0.5f*logdet - 0.5f*qs;
  }
}

extern "C" void kernel_launch(void* const* d_in, const int* in_sizes, int n_in,
                              void* d_out, int out_size){
  const float* x    = (const float*)d_in[0];
  const float* y    = (const float*)d_in[1];
  const float* uhi  = (const float*)d_in[2];
  const float* W_ih = (const float*)d_in[3];
  const float* W_hh = (const float*)d_in[4];
  const float* b_ih = (const float*)d_in[5];
  const float* b_hh = (const float*)d_in[6];
  const float* Hm   = (const float*)d_in[7];
  const float* q    = (const float*)d_in[8];
  const float* e    = (const float*)d_in[9];
  const float* r    = (const float*)d_in[10];
  const float* nh   = (const float*)d_in[11];
  const float* nc   = (const float*)d_in[12];
  float* out = (float*)d_out;

  static int smem_set = 0;
  if (!smem_set){
    cudaFuncSetAttribute(k_lstm, cudaFuncAttributeMaxDynamicSharedMemorySize, SMEM_SZ);
    smem_set = 1;
  }

  k_init<<<4096, 256>>>(uhi);
  k_bias<<<4, 256>>>(b_ih, b_hh);
  k_prep<<<512, 256>>>(W_ih, W_hh);
  dim3 gproj(32, 4);
  k_xproj<<<gproj, 256>>>(x, W_ih);

  k_lstm<<<128, 256, SMEM_SZ>>>();

  k_up<<<16384, 128>>>(nh, nc, q, e);
  k_hxi<<<64, 128>>>(Hm, y);
  k_P<<<64, 64>>>(r);
  k_inv<<<1, 128>>>();
  k_T2<<<64, 128>>>();
  k_T1<<<128, 128>>>();
  k_upd<<<128, 256>>>(out);
  k_rmean<<<16384, 128>>>(out);
  k_cov<<<128, 256>>>(out);
  k_Y<<<64, 128>>>(Hm, out);
  k_fcov<<<64, 64>>>(r, out);
  k_ll<<<1, 64>>>(y, out);
}

// round 5
// speedup vs baseline: 2.1405x; 1.1336x over previous
#include <cuda_runtime.h>
#include <cuda_bf16.h>
#include <cstdint>
#include <math.h>

#define LSn 2
#define BSn 64
#define Tn 64
#define NHn 128
#define HW (4096*128)
#define OUT_FO   0
#define OUT_FCOV 64
#define OUT_X    4160
#define OUT_COV  2101312
#define OUT_LL   4198464

// ---------------- device scratch ----------------
__device__ __align__(256) __nv_bfloat16 g_hbhi[2][2][HW];
__device__ __align__(256) __nv_bfloat16 g_hblo[2][2][HW];
__device__ __align__(256) __nv_bfloat16 g_sqhi[Tn][HW];
__device__ __align__(256) __nv_bfloat16 g_sqlo[Tn][HW];
__device__ __align__(256) __nv_bfloat16 g_Whhi[2][512*128];
__device__ __align__(256) __nv_bfloat16 g_Whlo[2][512*128];
__device__ __align__(256) __nv_bfloat16 g_Wihi[512*128];
__device__ __align__(256) __nv_bfloat16 g_Wilo[512*128];
__device__ float g_c0[2][HW];
__device__ float g_hT[2][HW];
__device__ float g_cT[2][HW];
__device__ __align__(256) float g_xproj[Tn*64*128*4];  // [((t*64+b)*128+n)*4+gate]
__device__ float g_bsum[2][512];
__device__ __align__(16) float g_bsum2[512];            // [n*4+gate] layer1
__device__ unsigned g_gcnt[32];
__device__ unsigned g_ggen[32];

__device__ float g_up[2*64*128*128];
__device__ float g_Am[2*64*128*128];
__device__ float g_HA[64*128];
__device__ float g_innov[64*128];
__device__ float g_P[64*64];
__device__ float g_Pinv[64*64];
__device__ float g_T2[64*128];
__device__ float g_T1[128*128];
__device__ float g_rmean[2*64*128];
__device__ float g_AY[64*128];
__device__ float g_fout[64];
__device__ float g_fcov[64*64];

__device__ __forceinline__ float sigm(float x){ return 1.f/(1.f + __expf(-x)); }
__device__ __forceinline__ float tanhs(float x){
  float e = __expf(2.f*fabsf(x));
  return copysignf(1.f - 2.f/(e+1.f), x);
}

#define SROW 272   // padded A/W row stride bytes
#define TROW 80    // staging row stride bytes

#define MMA_BF16(d, a, b0_, b1_) \
  asm volatile("mma.sync.aligned.m16n8k16.row.col.f32.bf16.bf16.f32 " \
    "{%0,%1,%2,%3},{%4,%5,%6,%7},{%8,%9},{%0,%1,%2,%3};" \
    : "+f"((d)[0]),"+f"((d)[1]),"+f"((d)[2]),"+f"((d)[3]) \
    : "r"((a)[0]),"r"((a)[1]),"r"((a)[2]),"r"((a)[3]),"r"(b0_),"r"(b1_))

// 128x128 bf16 row-major gmem -> smem rows padded to 272B
__device__ __forceinline__ void cp_tile(const __nv_bfloat16* __restrict__ src, char* dst, int tid){
  const uint4* s4 = (const uint4*)src;
  #pragma unroll
  for (int it=0; it<8; it++){
    int i = it*256 + tid;
    uint4 v = __ldcg(&s4[i]);
    int row = i>>4, ck = i&15;
    *(uint4*)(dst + row*SROW + ck*16) = v;
  }
}

__device__ __forceinline__ void group_bar(int rt, int tid){
  __syncthreads();
  if (tid==0){
    __threadfence();
    unsigned gen = *(volatile unsigned*)&g_ggen[rt];
    if (atomicInc(&g_gcnt[rt], 3u) == 3u){
      *(volatile unsigned*)&g_ggen[rt] = gen + 1u;
    } else {
      while (*(volatile unsigned*)&g_ggen[rt] == gen) __nanosleep(32);
    }
    __threadfence();
  }
  __syncthreads();
}

__device__ __forceinline__ void gemm_phase(float acc[8][2][4],
                                           const char* sAh, const char* sAl,
                                           const char* sBh, const char* sBl,
                                           int g, int tg, int wm, int wn){
  #pragma unroll
  for (int kc=0; kc<8; kc++){
    int kb = (kc*16 + 2*tg)*2;
    uint32_t ah[2][4], al[2][4];
    #pragma unroll
    for (int im=0; im<2; im++){
      int rA = (wm*32 + im*16 + g)*SROW + kb;
      ah[im][0] = *(const uint32_t*)(sAh + rA);
      ah[im][1] = *(const uint32_t*)(sAh + rA + 8*SROW);
      ah[im][2] = *(const uint32_t*)(sAh + rA + 16);
      ah[im][3] = *(const uint32_t*)(sAh + rA + 8*SROW + 16);
      al[im][0] = *(const uint32_t*)(sAl + rA);
      al[im][1] = *(const uint32_t*)(sAl + rA + 8*SROW);
      al[im][2] = *(const uint32_t*)(sAl + rA + 16);
      al[im][3] = *(const uint32_t*)(sAl + rA + 8*SROW + 16);
    }
    #pragma unroll
    for (int in=0; in<8; in++){
      int boff = (wn*64 + in*8 + g)*SROW + kb;
      uint32_t bh0 = *(const uint32_t*)(sBh + boff);
      uint32_t bh1 = *(const uint32_t*)(sBh + boff + 16);
      uint32_t bl0 = *(const uint32_t*)(sBl + boff);
      uint32_t bl1 = *(const uint32_t*)(sBl + boff + 16);
      #pragma unroll
      for (int im=0; im<2; im++){
        MMA_BF16(acc[in][im], ah[im], bh0, bh1);
        MMA_BF16(acc[in][im], ah[im], bl0, bl1);
        MMA_BF16(acc[in][im], al[im], bh0, bh1);
      }
    }
  }
}

// ---------------- prep ----------------
__global__ void k_init(const float* __restrict__ uhi){
  int idx = blockIdx.x*blockDim.x + threadIdx.x;
  int k = idx & 127, b = (idx>>7)&63, j = (idx>>13)&63, l = idx>>19;
  long base = (((long)(l*BSn+b))*NHn + k)*128;
  float h0 = uhi[base + j];
  int row = j*64+b;
  __nv_bfloat16 hi = __float2bfloat16(h0);
  g_hbhi[l][0][row*128+k] = hi;
  g_hblo[l][0][row*128+k] = __float2bfloat16(h0 - __bfloat162float(hi));
  g_c0[l][row*128+k] = uhi[base + 64 + j];
  if (idx < 32){ g_gcnt[idx] = 0; g_ggen[idx] = 0; }
}

__global__ void k_bias(const float* __restrict__ bih, const float* __restrict__ bhh){
  int idx = blockIdx.x*blockDim.x + threadIdx.x;
  if (idx < 1024){
    int l = idx>>9, c = idx&511;
    float v = bih[idx] + bhh[idx];
    g_bsum[l][c] = v;
    if (l==1) g_bsum2[(c&127)*4 + (c>>7)] = v;
  }
}

__global__ void k_prep(const float* __restrict__ W_ih, const float* __restrict__ W_hh){
  int idx = blockIdx.x*blockDim.x + threadIdx.x;   // 131072
  int k = idx & 127, cg = (idx>>7)&511, l = idx>>16;
  int ct = cg>>7, c = cg&127;
  int nat = (c&3)*128 + ct*32 + (c>>2);
  float wh = W_hh[l*65536 + nat*128 + k];
  __nv_bfloat16 hhi = __float2bfloat16(wh);
  g_Whhi[l][cg*128+k] = hhi;
  g_Whlo[l][cg*128+k] = __float2bfloat16(wh - __bfloat162float(hhi));
  if (l==1){
    float wi = W_ih[65536 + nat*128 + k];
    __nv_bfloat16 ihi = __float2bfloat16(wi);
    g_Wihi[cg*128+k] = ihi;
    g_Wilo[cg*128+k] = __float2bfloat16(wi - __bfloat162float(ihi));
  }
}

#define GEMM_CHUNK(AS,BS_,ACC,TX,TY)                                   \
  _Pragma("unroll 4")                                                  \
  for (int k2=0;k2<32;k2++){                                           \
    float a_[8], b_[8];                                                \
    *(float4*)&a_[0] = *(const float4*)&AS[k2][(TY)*8];                \
    *(float4*)&a_[4] = *(const float4*)&AS[k2][(TY)*8+4];              \
    *(float4*)&b_[0] = *(const float4*)&BS_[k2][(TX)*8];               \
    *(float4*)&b_[4] = *(const float4*)&BS_[k2][(TX)*8+4];             \
    _Pragma("unroll")                                                  \
    for (int ii=0;ii<8;ii++){                                          \
      _Pragma("unroll")                                                \
      for (int jj=0;jj<8;jj++) ACC[ii][jj] += a_[ii]*b_[jj];           \
    }                                                                  \
  }

__global__ __launch_bounds__(256) void k_xproj(const float* __restrict__ x,
                                               const float* __restrict__ Wi0){
  __shared__ __align__(16) float As[32][132];
  __shared__ __align__(16) float Bs[32][132];
  int tid = threadIdx.x, tx = tid & 15, ty = tid >> 4;
  int rb = blockIdx.x*128, cb = blockIdx.y*128;
  float acc[8][8] = {};
  for (int kc=0; kc<128; kc+=32){
    for (int i=tid;i<4096;i+=256){
      int r = i>>5, kk = i&31;
      int gr = rb + r, b = gr & 63, t = gr >> 6;
      As[kk][r] = x[(b*Tn + t)*128 + kc + kk];
    }
    for (int i=tid;i<4096;i+=256){
      int c = i>>5, kk = i&31;
      Bs[kk][c] = Wi0[(cb + c)*128 + kc + kk];
    }
    __syncthreads();
    GEMM_CHUNK(As,Bs,acc,tx,ty);
    __syncthreads();
  }
  #pragma unroll
  for (int r=0;r<8;r++){
    int gr = rb + ty*8 + r, b = gr & 63, t = gr >> 6;
    #pragma unroll
    for (int u=0;u<8;u++){
      int gc = cb + tx*8 + u;
      int gate = gc>>7, n = gc&127;
      g_xproj[(((long)t*64+b)*128 + n)*4 + gate] = acc[r][u] + g_bsum[0][gc];
    }
  }
}

// ---------------- persistent HMMA LSTM ----------------
#define SM_AH 0
#define SM_AL 34816
#define SM_W0 69632
#define SM_W1 104448
#define SM_W2 139264
#define SM_W3 174080
#define SMEM_SZ 208896

__global__ __launch_bounds__(256,1) void k_lstm(){
  extern __shared__ __align__(16) char smem[];
  char* sAh = smem + SM_AH;  char* sAl = smem + SM_AL;
  char* sW0 = smem + SM_W0;  char* sW1 = smem + SM_W1;
  char* sW2 = smem + SM_W2;  char* sW3 = smem + SM_W3;
  char* stHi = sAh;                // staging aliases A buffers after MMAs
  char* stLo = sAh + 10240;
  int tid = threadIdx.x, wid = tid>>5, lane = tid&31;
  int g = lane>>2, tg = lane&3;
  int wm = wid&3, wn = wid>>2;
  int rt = blockIdx.x>>2, ct = blockIdx.x&3;
  int s = tg&1, csel = tg>>1;
  int rowbase = rt*128 + wm*32 + g + 8*s;
  int nbase   = ct*32 + wn*16 + csel;
  int src_if = (g<<2) + (csel<<1);
  int src_go = src_if + 1;
  float creg[16];

  for (int l=0; l<2; l++){
    cp_tile(&g_Whhi[l][ct*16384], sW0, tid);
    cp_tile(&g_Whlo[l][ct*16384], sW1, tid);
    if (l==1){
      cp_tile(&g_Wihi[ct*16384], sW2, tid);
      cp_tile(&g_Wilo[ct*16384], sW3, tid);
    }
    #pragma unroll
    for (int im=0; im<2; im++)
      #pragma unroll
      for (int in=0; in<8; in++)
        creg[im*8+in] = g_c0[l][(long)(rowbase+im*16)*128 + nbase + in*2];
    __syncthreads();

    for (int t=0; t<64; t++){
      int rp = t&1, wp = rp^1;
      if (l==0){
        const __nv_bfloat16* sh = (t==0) ? &g_hbhi[0][0][rt*16384] : &g_sqhi[t-1][rt*16384];
        const __nv_bfloat16* sl = (t==0) ? &g_hblo[0][0][rt*16384] : &g_sqlo[t-1][rt*16384];
        cp_tile(sh, sAh, tid);
        cp_tile(sl, sAl, tid);
      } else {
        cp_tile(&g_hbhi[1][rp][rt*16384], sAh, tid);
        cp_tile(&g_hblo[1][rp][rt*16384], sAl, tid);
      }
      __syncthreads();
      float acc[8][2][4];
      #pragma unroll
      for (int in=0;in<8;in++)
        #pragma unroll
        for (int im=0;im<2;im++)
          #pragma unroll
          for (int r=0;r<4;r++) acc[in][im][r] = 0.f;
      gemm_phase(acc, sAh, sAl, sW0, sW1, g, tg, wm, wn);
      if (l==1){
        __syncthreads();
        cp_tile(&g_sqhi[t][rt*16384], sAh, tid);
        cp_tile(&g_sqlo[t][rt*16384], sAl, tid);
        __syncthreads();
        gemm_phase(acc, sAh, sAl, sW2, sW3, g, tg, wm, wn);
      }
      __syncthreads();   // A buffers free -> staging

      #pragma unroll
      for (int im=0; im<2; im++){
        int row = rowbase + im*16;
        int b = row & 63;
        const float4* xr = (l==0) ? ((const float4*)g_xproj) + (((long)t*64+b)<<7)
                                  : (const float4*)g_bsum2;
        #pragma unroll
        for (int in=0; in<8; in++){
          float* A4 = acc[in][im];
          float v0 = __shfl_sync(0xFFFFFFFFu, A4[0], src_if);
          float v2 = __shfl_sync(0xFFFFFFFFu, A4[2], src_if);
          float v1 = __shfl_sync(0xFFFFFFFFu, A4[1], src_if);
          float v3 = __shfl_sync(0xFFFFFFFFu, A4[3], src_if);
          float w0 = __shfl_sync(0xFFFFFFFFu, A4[0], src_go);
          float w2 = __shfl_sync(0xFFFFFFFFu, A4[2], src_go);
          float w1 = __shfl_sync(0xFFFFFFFFu, A4[1], src_go);
          float w3 = __shfl_sync(0xFFFFFFFFu, A4[3], src_go);
          float gi  = s ? v2 : v0;
          float gf  = s ? v3 : v1;
          float gg  = s ? w2 : w0;
          float go_ = s ? w3 : w1;
          int n = nbase + in*2;
          float4 xg = xr[n];
          gi += xg.x; gf += xg.y; gg += xg.z; go_ += xg.w;
          int idx = im*8 + in;
          float cc = sigm(gf)*creg[idx] + sigm(gi)*tanhs(gg);
          creg[idx] = cc;
          float hv = sigm(go_)*tanhs(cc);
          __nv_bfloat16 bh = __float2bfloat16(hv);
          __nv_bfloat16 bl = __float2bfloat16(hv - __bfloat162float(bh));
          int rl = row - rt*128;
          int nl = n - ct*32;
          *(__nv_bfloat16*)(stHi + rl*TROW + nl*2) = bh;
          *(__nv_bfloat16*)(stLo + rl*TROW + nl*2) = bl;
          if (t==63){
            long off = (long)row*128 + n;
            g_hT[l][off] = hv;
            g_cT[l][off] = cc;
          }
        }
      }
      __syncthreads();
      {
        __nv_bfloat16* dh; __nv_bfloat16* dl;
        if (l==0){ dh = &g_sqhi[t][0]; dl = &g_sqlo[t][0]; }
        else     { dh = &g_hbhi[1][wp][0]; dl = &g_hblo[1][wp][0]; }
        long gb = (long)rt*16384 + ct*32;
        #pragma unroll
        for (int it=0; it<2; it++){
          int i = it*256 + tid;
          int rowi = i>>2, seg = i&3;
          uint4 vh = *(const uint4*)(stHi + rowi*TROW + seg*16);
          uint4 vl = *(const uint4*)(stLo + rowi*TROW + seg*16);
          long o = gb + (long)rowi*128 + seg*8;
          __stcg((uint4*)(dh + o), vh);
          __stcg((uint4*)(dl + o), vl);
        }
      }
      group_bar(rt, tid);
    }
  }
}

// ---------------- EnKF tail ----------------
__global__ void k_up(const float* __restrict__ nh, const float* __restrict__ nc,
                     const float* qp, const float* ep){
  int m = blockIdx.x;
  int j = threadIdx.x;
  int n = m & 127, b = (m>>7)&63, l = m>>13;
  float q = fabsf(*qp), e = fabsf(*ep);
  float v;
  if (j < 64)
    v = g_hT[l][(j*64+b)*128 + n] + q * nh[((j*LSn + l)*BSn + b)*128 + n];
  else {
    int j2 = j - 64;
    v = g_cT[l][(j2*64+b)*128 + n] + e * nc[((j2*LSn + l)*BSn + b)*128 + n];
  }
  __shared__ float red[128];
  red[j] = v; __syncthreads();
  for (int st=64;st>0;st>>=1){ if (j<st) red[j]+=red[j+st]; __syncthreads(); }
  float mean = red[0]*(1.f/128.f);
  g_up[(long)m*128 + j] = v;
  g_Am[(long)m*128 + j] = v - mean;
}

__global__ void k_hxi(const float* __restrict__ Hm, const float* __restrict__ y){
  int b = blockIdx.x, N = threadIdx.x;
  __shared__ float Hs[128];
  Hs[N] = Hm[N]; __syncthreads();
  float sm = 0.f;
  for (int n=0;n<128;n++) sm += g_up[((long)(b*128+n))*128 + N] * Hs[n];
  __shared__ float red[128];
  red[N] = sm; __syncthreads();
  for (int st=64;st>0;st>>=1){ if (N<st) red[N]+=red[N+st]; __syncthreads(); }
  float mean = red[0]*(1.f/128.f);
  g_HA[b*128+N] = sm - mean;
  g_innov[b*128+N] = y[b] - sm;
}

__global__ void k_P(const float* rp){
  int c = blockIdx.x, d = threadIdx.x;
  float sm = 0.f;
  for (int N=0;N<128;N++) sm += g_HA[c*128+N]*g_HA[d*128+N];
  float r = *rp;
  g_P[c*64+d] = sm*(1.f/127.f) + (c==d ? r*r : 0.f);
}

__global__ void k_inv(){
  __shared__ float M[64][128];
  __shared__ float fcol[64];
  __shared__ int spiv;
  int tid = threadIdx.x;
  for (int e=tid;e<8192;e+=128){
    int r = e>>7, c = e&127;
    M[r][c] = (c<64) ? g_P[r*64+c] : ((c-64)==r ? 1.f : 0.f);
  }
  __syncthreads();
  for (int k=0;k<64;k++){
    if (tid==0){
      int p = k; float best = fabsf(M[k][k]);
      for (int rr=k+1;rr<64;rr++){ float v=fabsf(M[rr][k]); if (v>best){best=v;p=rr;} }
      spiv = p;
    }
    __syncthreads();
    int p = spiv;
    if (p != k){ float tmp = M[k][tid]; M[k][tid] = M[p][tid]; M[p][tid] = tmp; }
    __syncthreads();
    float pv = M[k][k];
    __syncthreads();
    M[k][tid] = M[k][tid] / pv;
    __syncthreads();
    if (tid < 64) fcol[tid] = M[tid][k];
    __syncthreads();
    for (int e=tid;e<8192;e+=128){
      int r = e>>7, c = e&127;
      if (r != k) M[r][c] -= fcol[r]*M[k][c];
    }
    __syncthreads();
  }
  for (int e=tid;e<4096;e+=128){
    int r = e>>6, d = e&63;
    g_Pinv[r*64+d] = M[r][64+d];
  }
}

__global__ void k_T2(){
  int c = blockIdx.x, M = threadIdx.x;
  float sm = 0.f;
  for (int d=0;d<64;d++) sm += g_Pinv[c*64+d]*g_innov[d*128+M];
  g_T2[c*128+M] = sm;
}

__global__ void k_T1(){
  int N = blockIdx.x, M = threadIdx.x;
  __shared__ float HAc[64];
  if (M < 64) HAc[M] = g_HA[M*128 + N];
  __syncthreads();
  float sm = 0.f;
  for (int c=0;c<64;c++) sm += HAc[c]*g_T2[c*128+M];
  g_T1[N*128+M] = sm;
}

__global__ __launch_bounds__(256) void k_upd(float* __restrict__ out){
  __shared__ __align__(16) float As[32][132];
  __shared__ __align__(16) float Bs[32][132];
  int lb = blockIdx.x;
  int tid = threadIdx.x, tx = tid & 15, ty = tid >> 4;
  const float* Ab = &g_Am[(long)lb*16384];
  float acc[8][8] = {};
  for (int kc=0; kc<128; kc+=32){
    for (int i=tid;i<4096;i+=256){
      int r = i>>5, kk = i&31;
      As[kk][r] = Ab[r*128 + kc + kk];
    }
    for (int i=tid;i<4096;i+=256){
      int c = i&127, kk = i>>7;
      Bs[kk][c] = g_T1[(kc+kk)*128 + c];
    }
    __syncthreads();
    GEMM_CHUNK(As,Bs,acc,tx,ty);
    __syncthreads();
  }
  #pragma unroll
  for (int r=0;r<8;r++){
    int n = ty*8 + r;
    #pragma unroll
    for (int u=0;u<8;u++){
      int Mc = tx*8 + u;
      long idx = (long)lb*16384 + n*128 + Mc;
      out[OUT_X + idx] = g_up[idx] + acc[r][u]*(1.f/127.f);
    }
  }
}

__global__ void k_rmean(const float* __restrict__ out){
  int row = blockIdx.x;
  int M = threadIdx.x;
  float v = out[OUT_X + (long)row*128 + M];
  __shared__ float red[128];
  red[M] = v; __syncthreads();
  for (int st=64;st>0;st>>=1){ if (M<st) red[M]+=red[M+st]; __syncthreads(); }
  if (M==0) g_rmean[row] = red[0]*(1.f/128.f);
}

__global__ __launch_bounds__(256) void k_cov(float* __restrict__ out){
  __shared__ __align__(16) float S[32][132];
  int lb = blockIdx.x;
  int tid = threadIdx.x, tx = tid & 15, ty = tid >> 4;
  const float* Xb = out + OUT_X + (long)lb*16384;
  const float* mu = &g_rmean[lb*128];
  float acc[8][8] = {};
  for (int kc=0; kc<128; kc+=32){
    for (int i=tid;i<4096;i+=256){
      int r = i>>5, kk = i&31;
      S[kk][r] = Xb[r*128 + kc + kk] - mu[r];
    }
    __syncthreads();
    GEMM_CHUNK(S,S,acc,tx,ty);
    __syncthreads();
  }
  #pragma unroll
  for (int r=0;r<8;r++){
    int n = ty*8 + r;
    #pragma unroll
    for (int u=0;u<8;u++){
      int m = tx*8 + u;
      out[OUT_COV + (long)lb*16384 + n*128 + m] = acc[r][u]*(1.f/127.f);
    }
  }
}

__global__ void k_Y(const float* __restrict__ Hm, float* __restrict__ out){
  int b = blockIdx.x, N = threadIdx.x;
  __shared__ float Hs[128];
  Hs[N] = Hm[N]; __syncthreads();
  float sm = 0.f;
  for (int n=0;n<128;n++) sm += out[OUT_X + (long)b*16384 + n*128 + N] * Hs[n];
  __shared__ float red[128];
  red[N] = sm; __syncthreads();
  for (int st=64;st>0;st>>=1){ if (N<st) red[N]+=red[N+st]; __syncthreads(); }
  float mean = red[0]*(1.f/128.f);
  g_AY[b*128+N] = sm - mean;
  if (N==0){ g_fout[b] = mean; out[OUT_FO + b] = mean; }
}

__global__ void k_fcov(const float* rp, float* __restrict__ out){
  int c = blockIdx.x, d = threadIdx.x;
  float sm = 0.f;
  for (int N=0;N<128;N++) sm += g_AY[c*128+N]*g_AY[d*128+N];
  float r = *rp;
  float v = sm*(1.f/127.f) + (c==d ? r*r : 0.f);
  g_fcov[c*64+d] = v;
  out[OUT_FCOV + c*64+d] = v;
}

__global__ void k_ll(const float* __restrict__ y, float* __restrict__ out){
  __shared__ float A[64][65];
  __shared__ float red[64];
  int tid = threadIdx.x;
  for (int c=0;c<64;c++) A[tid][c] = g_fcov[tid*64+c];
  __syncthreads();
  for (int k=0;k<64;k++){
    if (tid==k) A[k][k] = sqrtf(A[k][k]);
    __syncthreads();
    float lkk = A[k][k];
    if (tid>k) A[tid][k] /= lkk;
    __syncthreads();
    if (tid>k){
      float lrk = A[tid][k];
      for (int c=k+1;c<=tid;c++) A[tid][c] -= lrk*A[c][k];
    }
    __syncthreads();
  }
  red[tid] = 2.f*logf(A[tid][tid]);
  __syncthreads();
  for (int st=32;st>0;st>>=1){ if (tid<st) red[tid]+=red[tid+st]; __syncthreads(); }
  if (tid==0){
    float logdet = red[0];
    float z[64];
    for (int k=0;k<64;k++){
      float sm = y[k] - g_fout[k];
      for (int j=0;j<k;j++) sm -= A[k][j]*z[j];
      z[k] = sm / A[k][k];
    }
    float qs = 0.f;
    for (int k=0;k<64;k++) qs += z[k]*z[k];
    out[OUT_LL] = -0.5f*logdet - 0.5f*qs;
  }
}

extern "C" void kernel_launch(void* const* d_in, const int* in_sizes, int n_in,
                              void* d_out, int out_size){
  const float* x    = (const float*)d_in[0];
  const float* y    = (const float*)d_in[1];
  const float* uhi  = (const float*)d_in[2];
  const float* W_ih = (const float*)d_in[3];
  const float* W_hh = (const float*)d_in[4];
  const float* b_ih = (const float*)d_in[5];
  const float* b_hh = (const float*)d_in[6];
  const float* Hm   = (const float*)d_in[7];
  const float* q    = (const float*)d_in[8];
  const float* e    = (const float*)d_in[9];
  const float* r    = (const float*)d_in[10];
  const float* nh   = (const float*)d_in[11];
  const float* nc   = (const float*)d_in[12];
  float* out = (float*)d_out;

  static int smem_set = 0;
  if (!smem_set){
    cudaFuncSetAttribute(k_lstm, cudaFuncAttributeMaxDynamicSharedMemorySize, SMEM_SZ);
    smem_set = 1;
  }

  k_init<<<4096, 256>>>(uhi);
  k_bias<<<4, 256>>>(b_ih, b_hh);
  k_prep<<<512, 256>>>(W_ih, W_hh);
  dim3 gproj(32, 4);
  k_xproj<<<gproj, 256>>>(x, W_ih);

  k_lstm<<<128, 256, SMEM_SZ>>>();

  k_up<<<16384, 128>>>(nh, nc, q, e);
  k_hxi<<<64, 128>>>(Hm, y);
  k_P<<<64, 64>>>(r);
  k_inv<<<1, 128>>>();
  k_T2<<<64, 128>>>();
  k_T1<<<128, 128>>>();
  k_upd<<<128, 256>>>(out);
  k_rmean<<<16384, 128>>>(out);
  k_cov<<<128, 256>>>(out);
  k_Y<<<64, 128>>>(Hm, out);
  k_fcov<<<64, 64>>>(r, out);
  k_ll<<<1, 64>>>(y, out);
}